// round 9
// baseline (speedup 1.0000x reference)
#include <cuda_runtime.h>
#include <stdint.h>

#define NUM_FIELDS 10
#define VOCAB      100000
#define EMBED      16            // floats per embedding row (64 bytes)
#define BATCH      16384
#define NPAIRS     45            // C(10,2)
#define B_PER_BLK  64            // quads per 256-thread block

// triu_indices(10, k=1): pair p -> (ii[p], jj[p]) with ii < jj
__constant__ unsigned char c_ii[NPAIRS] = {
    0,0,0,0,0,0,0,0,0,
    1,1,1,1,1,1,1,1,
    2,2,2,2,2,2,2,
    3,3,3,3,3,3,
    4,4,4,4,4,
    5,5,5,5,
    6,6,6,
    7,7,
    8
};
__constant__ unsigned char c_jj[NPAIRS] = {
    1,2,3,4,5,6,7,8,9,
    2,3,4,5,6,7,8,9,
    3,4,5,6,7,8,9,
    4,5,6,7,8,9,
    5,6,7,8,9,
    6,7,8,9,
    7,8,9,
    8,9,
    9
};

// R6 layout (proven best): PAIR-MAJOR grid, blockIdx.y = pair slot,
// blockIdx.x = 64-wide b tile. Resident CTAs span ~5 pair slots -> tight
// DRAM-row/TLB locality on the gathers.
// R5 store policy (lowest measured HBM bytes): __stwt write-through,
// no L2 allocation — pair-major writes are lone 64B chunks per 128B line,
// so allocating them in L2 buys nothing.
__global__ __launch_bounds__(256)
void ffm_kernel(const int*    __restrict__ x,      // int32 (16384, 10)
                const float4* __restrict__ emb,    // (10, 1e6, 16) as float4[40M]
                float4*       __restrict__ out)    // (16384, 45, 16) as float4
{
    int q    = threadIdx.x & 3;
    int quad = threadIdx.x >> 2;                   // 0..63
    int b    = blockIdx.x * B_PER_BLK + quad;      // exact fit: 256*64 = 16384
    int p    = blockIdx.y;                         // uniform per block
    int i    = c_ii[p];
    int j    = c_jj[p];

    // broadcast within quad
    int xi = x[b * NUM_FIELDS + i];
    int xj = x[b * NUM_FIELDS + j];
    xi = min(max(xi, 0), VOCAB - 1);
    xj = min(max(xj, 0), VOCAB - 1);

    // out[b,p] = emb[j, x[b,i]+i*V] * emb[i, x[b,j]+j*V]
    size_t rowA = (size_t)j * (NUM_FIELDS * (size_t)VOCAB) + (size_t)xi + (size_t)i * VOCAB;
    size_t rowB = (size_t)i * (NUM_FIELDS * (size_t)VOCAB) + (size_t)xj + (size_t)j * VOCAB;

    // Streaming loads: rows are used exactly once.
    float4 a = __ldcs(emb + rowA * (EMBED / 4) + q);
    float4 v = __ldcs(emb + rowB * (EMBED / 4) + q);

    float4 o;
    o.x = a.x * v.x;
    o.y = a.y * v.y;
    o.z = a.z * v.z;
    o.w = a.w * v.w;

    // Write-through, no L2 allocate: output is never read back.
    __stwt(out + ((size_t)b * NPAIRS + p) * (EMBED / 4) + q, o);
}

extern "C" void kernel_launch(void* const* d_in, const int* in_sizes, int n_in,
                              void* d_out, int out_size)
{
    const int*    x   = (const int*)d_in[0];      // indices (int32 on device)
    const float4* emb = (const float4*)d_in[1];   // float32 (10, 1e6, 16)
    float4*       out = (float4*)d_out;           // float32 (16384, 45, 16)

    dim3 grid(BATCH / B_PER_BLK, NPAIRS);         // (256, 45)
    ffm_kernel<<<grid, 256>>>(x, emb, out);
}

// round 10
// speedup vs baseline: 1.0166x; 1.0166x over previous
#include <cuda_runtime.h>
#include <stdint.h>

#define NUM_FIELDS 10
#define VOCAB      100000
#define EMBED      16            // floats per embedding row (64 bytes)
#define BATCH      16384
#define NPAIRS     45            // C(10,2)
#define BLOCK      128
#define B_PER_BLK  (BLOCK / 4)   // 32 quads per block

// triu_indices(10, k=1): pair p -> (ii[p], jj[p]) with ii < jj
__constant__ unsigned char c_ii[NPAIRS] = {
    0,0,0,0,0,0,0,0,0,
    1,1,1,1,1,1,1,1,
    2,2,2,2,2,2,2,
    3,3,3,3,3,3,
    4,4,4,4,4,
    5,5,5,5,
    6,6,6,
    7,7,
    8
};
__constant__ unsigned char c_jj[NPAIRS] = {
    1,2,3,4,5,6,7,8,9,
    2,3,4,5,6,7,8,9,
    3,4,5,6,7,8,9,
    4,5,6,7,8,9,
    5,6,7,8,9,
    6,7,8,9,
    7,8,9,
    8,9,
    9
};

// Combination of the two individually-best measured variants:
//   R8 geometry: PAIR-MAJOR grid with 128-thread blocks -> resident CTAs
//     span only ~2.3 pair slots (~30MB live gather footprint) -> best
//     DRAM-row/TLB locality measured (DRAM=70%, 5543 GB/s).
//   R9 stores: __stwt write-through, no L2 allocate -> lowest HBM bytes;
//     pair-major writes are lone 64B chunks per 128B line, L2 allocation
//     of them buys nothing.
// 4 lanes per (b,p): lane q handles float4 q of both rows (coalesced 64B).
__global__ __launch_bounds__(BLOCK)
void ffm_kernel(const int*    __restrict__ x,      // int32 (16384, 10)
                const float4* __restrict__ emb,    // (10, 1e6, 16) as float4[40M]
                float4*       __restrict__ out)    // (16384, 45, 16) as float4
{
    int q    = threadIdx.x & 3;
    int quad = threadIdx.x >> 2;                   // 0..31
    int b    = blockIdx.x * B_PER_BLK + quad;      // exact fit: 512*32 = 16384
    int p    = blockIdx.y;                         // uniform per block
    int i    = c_ii[p];
    int j    = c_jj[p];

    // broadcast within quad
    int xi = x[b * NUM_FIELDS + i];
    int xj = x[b * NUM_FIELDS + j];
    xi = min(max(xi, 0), VOCAB - 1);
    xj = min(max(xj, 0), VOCAB - 1);

    // out[b,p] = emb[j, x[b,i]+i*V] * emb[i, x[b,j]+j*V]
    size_t rowA = (size_t)j * (NUM_FIELDS * (size_t)VOCAB) + (size_t)xi + (size_t)i * VOCAB;
    size_t rowB = (size_t)i * (NUM_FIELDS * (size_t)VOCAB) + (size_t)xj + (size_t)j * VOCAB;

    // Streaming loads: rows are used exactly once.
    float4 a = __ldcs(emb + rowA * (EMBED / 4) + q);
    float4 v = __ldcs(emb + rowB * (EMBED / 4) + q);

    float4 o;
    o.x = a.x * v.x;
    o.y = a.y * v.y;
    o.z = a.z * v.z;
    o.w = a.w * v.w;

    // Write-through, no L2 allocate: output is never read back.
    __stwt(out + ((size_t)b * NPAIRS + p) * (EMBED / 4) + q, o);
}

extern "C" void kernel_launch(void* const* d_in, const int* in_sizes, int n_in,
                              void* d_out, int out_size)
{
    const int*    x   = (const int*)d_in[0];      // indices (int32 on device)
    const float4* emb = (const float4*)d_in[1];   // float32 (10, 1e6, 16)
    float4*       out = (float4*)d_out;           // float32 (16384, 45, 16)

    dim3 grid(BATCH / B_PER_BLK, NPAIRS);         // (512, 45)
    ffm_kernel<<<grid, BLOCK>>>(x, emb, out);
}